// round 15
// baseline (speedup 1.0000x reference)
#include <cuda_runtime.h>
#include <cuda_bf16.h>
#include <cstdint>

#define BB 2
#define SS 2048
#define EE 1024
#define HH 16
#define DD 64
#define MTOT (BB*SS)    // 4096
#define HD (HH*DD)      // 1024

// bf16 operands
__device__ __nv_bfloat16 g_Qh[(size_t)MTOT * HD];
__device__ __nv_bfloat16 g_Kh[(size_t)MTOT * HD];
__device__ __nv_bfloat16 g_Vh[(size_t)MTOT * HD];
__device__ __nv_bfloat16 g_EmbH[(size_t)MTOT * HD];   // emb bf16 (QKV A operand)
__device__ __nv_bfloat16 g_AttnH[(size_t)MTOT * HD];  // attn out bf16 (out-proj A)
// weights bf16: Wq @0, Wk @1M, Wv @2M, Wu @3M
__device__ __nv_bfloat16 g_Wh[(size_t)4 * EE * HD];

// ===========================================================================
// helpers (arch-portable: cp.async + ldmatrix + mma.sync, sm_80+ PTX)
// ===========================================================================
__device__ __forceinline__ uint32_t smem_to_u32(const void* p) {
    uint32_t a;
    asm("{ .reg .u64 t; cvta.to.shared.u64 t, %1; cvt.u32.u64 %0, t; }"
        : "=r"(a) : "l"(p));
    return a;
}
__device__ __forceinline__ void cp16(uint32_t d, const void* s) {
    asm volatile("cp.async.ca.shared.global [%0], [%1], 16;" :: "r"(d), "l"(s));
}
__device__ __forceinline__ void cp_commit() {
    asm volatile("cp.async.commit_group;" ::: "memory");
}
template <int N>
__device__ __forceinline__ void cp_wait() {
    asm volatile("cp.async.wait_group %0;" :: "n"(N) : "memory");
}
__device__ __forceinline__ void ldm_x4(uint32_t* r, uint32_t addr) {
    asm volatile("ldmatrix.sync.aligned.m8n8.x4.shared.b16 {%0,%1,%2,%3}, [%4];"
        : "=r"(r[0]), "=r"(r[1]), "=r"(r[2]), "=r"(r[3]) : "r"(addr));
}
__device__ __forceinline__ void ldm_x4_t(uint32_t* r, uint32_t addr) {
    asm volatile("ldmatrix.sync.aligned.m8n8.x4.trans.shared.b16 {%0,%1,%2,%3}, [%4];"
        : "=r"(r[0]), "=r"(r[1]), "=r"(r[2]), "=r"(r[3]) : "r"(addr));
}
__device__ __forceinline__ void mma_bf16(float* d, const uint32_t* a, const uint32_t* b) {
    asm volatile(
        "mma.sync.aligned.m16n8k16.row.col.f32.bf16.bf16.f32 "
        "{%0,%1,%2,%3}, {%4,%5,%6,%7}, {%8,%9}, {%0,%1,%2,%3};"
        : "+f"(d[0]), "+f"(d[1]), "+f"(d[2]), "+f"(d[3])
        : "r"(a[0]), "r"(a[1]), "r"(a[2]), "r"(a[3]), "r"(b[0]), "r"(b[1]));
}
// 2^y, degree-4 Taylor on [-0.5,0.5] (rel err ~6e-5). |y| bounded by LN'd Q/K.
__device__ __forceinline__ float exp2_nomax(float y) {
    float t = y + 12582912.0f;                 // 1.5*2^23: round-to-nearest
    int ibits = __float_as_int(t) << 23;
    float f = y - (t - 12582912.0f);           // f in [-0.5, 0.5]
    float p = 9.6181e-3f;
    p = fmaf(p, f, 5.5504108664e-2f);
    p = fmaf(p, f, 2.4022650696e-1f);
    p = fmaf(p, f, 6.9314718056e-1f);
    p = fmaf(p, f, 1.0f);
    return __int_as_float(__float_as_int(p) + ibits);
}

// ===========================================================================
// fp32 -> bf16 conversion: ONE kernel for all weights + emb.
// ===========================================================================
__global__ __launch_bounds__(256) void conv_all_kernel(
    const float* __restrict__ Wq, const float* __restrict__ Wk,
    const float* __restrict__ Wv, const float* __restrict__ Wu,
    const float* __restrict__ emb)
{
    const int z = blockIdx.y;
    const size_t M1 = (size_t)EE * HD;  // 1M elements
    const float* src;
    __nv_bfloat16* dst;
    if (z < 4) {
        src = (z == 0) ? Wq : (z == 1) ? Wk : (z == 2) ? Wv : Wu;
        dst = g_Wh + (size_t)z * M1;
    } else {
        src = emb + (size_t)(z - 4) * M1;
        dst = g_EmbH + (size_t)(z - 4) * M1;
    }
    int i = blockIdx.x * blockDim.x + threadIdx.x;   // over 1M/8
    float4 a = ((const float4*)src)[2 * i + 0];
    float4 b = ((const float4*)src)[2 * i + 1];
    __nv_bfloat162* d = (__nv_bfloat162*)dst + 4 * i;
    d[0] = __halves2bfloat162(__float2bfloat16(a.x), __float2bfloat16(a.y));
    d[1] = __halves2bfloat162(__float2bfloat16(a.z), __float2bfloat16(a.w));
    d[2] = __halves2bfloat162(__float2bfloat16(b.x), __float2bfloat16(b.y));
    d[3] = __halves2bfloat162(__float2bfloat16(b.z), __float2bfloat16(b.w));
}

// ===========================================================================
// bf16 mma.sync GEMM: C[m,n] = sum_k A[m,k]*B[n,k]
// Block 128x128, BK=32, 8 warps, cp.async 3-stage pipeline, ONE barrier per
// k-iteration. __launch_bounds__(256,2). (Unchanged from R14 — measured best.)
// ===========================================================================
#define ASTR 40
#define TILE_BYTES (128 * ASTR * 2)       // 10240
#define STAGE_BYTES (2 * TILE_BYTES)      // 20480
#define NSTAGE 3
#define GEMM_SMEM (NSTAGE * STAGE_BYTES)  // 61440

__global__ __launch_bounds__(256, 2) void mma_gemm_kernel(
    const __nv_bfloat16* __restrict__ A,
    const __nv_bfloat16* __restrict__ Wall,
    float* Cout,
    const float* __restrict__ emb, const float* __restrict__ bu,
    const float* __restrict__ qn_w, const float* __restrict__ qn_b,
    const float* __restrict__ kn_w, const float* __restrict__ kn_b)
{
    extern __shared__ char smem[];
    const uint32_t sb = smem_to_u32(smem);
    const int tid = threadIdx.x;
    const int wid = tid >> 5, lane = tid & 31;
    const int bn = blockIdx.x * 128;
    const int bm = blockIdx.y * 128;
    const int z = blockIdx.z;

    const __nv_bfloat16* Bp = Wall + (size_t)z * EE * HD;
    const int wm = wid & 3;
    const int wn = wid >> 2;

    float acc[2][8][4];
#pragma unroll
    for (int mt = 0; mt < 2; mt++)
#pragma unroll
        for (int nt = 0; nt < 8; nt++)
#pragma unroll
            for (int e = 0; e < 4; e++) acc[mt][nt][e] = 0.0f;

#define LOAD_STAGE(st, kt) do { \
    _Pragma("unroll") \
    for (int it = 0; it < 4; it++) { \
        int idx = tid + it * 256; \
        int tile = idx >> 9, rem = idx & 511, row = rem >> 2, seg = rem & 3; \
        const __nv_bfloat16* srcp = tile ? Bp : A; \
        int grow = (tile ? bn : bm) + row; \
        uint32_t dst = sb + (st) * STAGE_BYTES + tile * TILE_BYTES \
                       + (uint32_t)(row * ASTR + seg * 8) * 2; \
        cp16(dst, srcp + (size_t)grow * 1024 + (kt) + seg * 8); \
    } \
    cp_commit(); \
} while (0)

    LOAD_STAGE(0, 0);
    LOAD_STAGE(1, 32);

    int stage = 0;
    for (int ch = 0; ch < 32; ch++) {
        if (ch < 31) cp_wait<1>();
        else         cp_wait<0>();
        __syncthreads();   // single barrier per iteration

        const uint32_t aA = sb + stage * STAGE_BYTES;
        const uint32_t aB = aA + TILE_BYTES;

#pragma unroll
        for (int kk = 0; kk < 2; kk++) {
            const int k0 = kk * 16;
            uint32_t ah[2][4], bh[8][2];
#pragma unroll
            for (int mt = 0; mt < 2; mt++) {
                int mrow = wm * 32 + mt * 16 + ((lane >> 3) & 1) * 8 + (lane & 7);
                int mcol = k0 + (lane >> 4) * 8;
                ldm_x4(ah[mt], aA + (uint32_t)(mrow * ASTR + mcol) * 2);
            }
#pragma unroll
            for (int np = 0; np < 4; np++) {
                int nrow = wn * 64 + np * 16 + (lane >> 4) * 8 + (lane & 7);
                int ncol = k0 + ((lane >> 3) & 1) * 8;
                uint32_t r[4];
                ldm_x4(r, aB + (uint32_t)(nrow * ASTR + ncol) * 2);
                bh[np * 2][0] = r[0]; bh[np * 2][1] = r[1];
                bh[np * 2 + 1][0] = r[2]; bh[np * 2 + 1][1] = r[3];
            }
#pragma unroll
            for (int mt = 0; mt < 2; mt++)
#pragma unroll
                for (int nt = 0; nt < 8; nt++) mma_bf16(acc[mt][nt], ah[mt], bh[nt]);
        }

        // load-next: target stage (stage+2)%3 was consumed at iter ch-1;
        // every warp passed this iteration's barrier after that compute.
        if (ch < 30) {
            int nst = stage + 2; if (nst >= NSTAGE) nst -= NSTAGE;
            LOAD_STAGE(nst, (ch + 2) * 32);
        }
        if (++stage == NSTAGE) stage = 0;
    }

    const int tig = lane & 3, gid = lane >> 2;
    if (z == 2) {
        // V: write bf16 directly
#pragma unroll
        for (int mt = 0; mt < 2; mt++) {
            int r0 = bm + wm * 32 + mt * 16 + gid;
#pragma unroll
            for (int nt = 0; nt < 8; nt++) {
                int n = bn + wn * 64 + nt * 8 + tig * 2;
                *(__nv_bfloat162*)(g_Vh + (size_t)r0 * HD + n) =
                    __halves2bfloat162(__float2bfloat16(acc[mt][nt][0]),
                                       __float2bfloat16(acc[mt][nt][1]));
                *(__nv_bfloat162*)(g_Vh + (size_t)(r0 + 8) * HD + n) =
                    __halves2bfloat162(__float2bfloat16(acc[mt][nt][2]),
                                       __float2bfloat16(acc[mt][nt][3]));
            }
        }
    } else if (emb) {
        // out-projection epilogue: + bu + emb residual, fp32 output
#pragma unroll
        for (int mt = 0; mt < 2; mt++) {
            int r0 = bm + wm * 32 + mt * 16 + gid;
#pragma unroll
            for (int nt = 0; nt < 8; nt++) {
                int n = bn + wn * 64 + nt * 8 + tig * 2;
                float2 v0 = make_float2(acc[mt][nt][0], acc[mt][nt][1]);
                float2 v1 = make_float2(acc[mt][nt][2], acc[mt][nt][3]);
                float b0 = bu[n], b1 = bu[n + 1];
                float2 e0 = *(const float2*)(emb + (size_t)r0 * EE + n);
                float2 e1 = *(const float2*)(emb + (size_t)(r0 + 8) * EE + n);
                v0.x += b0 + e0.x; v0.y += b1 + e0.y;
                v1.x += b0 + e1.x; v1.y += b1 + e1.y;
                *(float2*)(Cout + (size_t)r0 * 1024 + n) = v0;
                *(float2*)(Cout + (size_t)(r0 + 8) * 1024 + n) = v1;
            }
        }
    } else {
        // fused LayerNorm epilogue (Q: z==0 with folded 0.125*log2e; K: z==1)
        const float scale = (z == 0) ? 0.1803368801111243f : 1.0f;
        const float* lw = (z == 0) ? qn_w : kn_w;
        const float* lb = (z == 0) ? qn_b : kn_b;
        __nv_bfloat16* dstb = (z == 0) ? g_Qh : g_Kh;
        float wv[16], bv[16];
#pragma unroll
        for (int nt = 0; nt < 8; nt++) {
            int c = nt * 8 + tig * 2;   // column within head
            float2 wp = *(const float2*)(lw + c);
            float2 bp = *(const float2*)(lb + c);
            wv[nt * 2] = wp.x; wv[nt * 2 + 1] = wp.y;
            bv[nt * 2] = bp.x; bv[nt * 2 + 1] = bp.y;
        }
#pragma unroll
        for (int mt = 0; mt < 2; mt++) {
            int r0 = bm + wm * 32 + mt * 16 + gid;
#pragma unroll
            for (int half = 0; half < 2; half++) {
                float sum = 0.0f, sq = 0.0f;
#pragma unroll
                for (int nt = 0; nt < 8; nt++) {
                    float v0 = acc[mt][nt][half * 2];
                    float v1 = acc[mt][nt][half * 2 + 1];
                    sum += v0 + v1;
                    sq = fmaf(v0, v0, sq); sq = fmaf(v1, v1, sq);
                }
                sum += __shfl_xor_sync(0xffffffffu, sum, 1);
                sum += __shfl_xor_sync(0xffffffffu, sum, 2);
                sq  += __shfl_xor_sync(0xffffffffu, sq, 1);
                sq  += __shfl_xor_sync(0xffffffffu, sq, 2);
                float mean = sum * (1.0f / 64.0f);
                float var = sq * (1.0f / 64.0f) - mean * mean;
                float inv = rsqrtf(var + 1e-5f) * scale;
                int row = r0 + half * 8;
#pragma unroll
                for (int nt = 0; nt < 8; nt++) {
                    int n = bn + wn * 64 + nt * 8 + tig * 2;
                    float v0 = acc[mt][nt][half * 2];
                    float v1 = acc[mt][nt][half * 2 + 1];
                    float y0 = fmaf((v0 - mean) * inv, wv[nt * 2],     bv[nt * 2] * scale);
                    float y1 = fmaf((v1 - mean) * inv, wv[nt * 2 + 1], bv[nt * 2 + 1] * scale);
                    *(__nv_bfloat162*)(dstb + (size_t)row * HD + n) =
                        __halves2bfloat162(__float2bfloat16(y0), __float2bfloat16(y1));
                }
            }
        }
    }
}

// ---------------------------------------------------------------------------
// Flash attention on mma.sync (bf16). grid (S/128, B*H), 256 threads (8 warps).
// Warp = 16 q rows. KV tile 128, per-16-col-chunk QK->exp2->PV.
// QK uses SPLIT ACCUMULATORS (kk 0-1 and kk 2-3 independent, merged before
// exp2): mma dependency chain depth 4 -> 2, doubling QK ILP.
// __launch_bounds__(256,2). Max-free softmax. Output bf16 into g_AttnH.
// ---------------------------------------------------------------------------
#define QSTR 72
#define ATILE (128 * QSTR * 2)
#define KV_OFF ATILE
#define KVSTAGE (2 * ATILE)
#define ATTN_SMEM (ATILE + 2 * KVSTAGE)

__global__ __launch_bounds__(256, 2) void attn_kernel()
{
    extern __shared__ char smem[];
    const uint32_t sb = smem_to_u32(smem);
    const int tid = threadIdx.x;
    const int wid = tid >> 5, lane = tid & 31;
    const int gid = lane >> 2, tig = lane & 3;
    const int q0 = blockIdx.x * 128;
    const int bh = blockIdx.y;
    const int b = bh >> 4, h = bh & 15;

    const __nv_bfloat16* Qg = g_Qh + (size_t)(b * SS + q0) * HD + h * DD;
    const __nv_bfloat16* Kg = g_Kh + (size_t)(b * SS) * HD + h * DD;
    const __nv_bfloat16* Vg = g_Vh + (size_t)(b * SS) * HD + h * DD;

#pragma unroll
    for (int p = 0; p < 4; p++) {
        int idx = tid + p * 256;
        int row = idx >> 3, seg = idx & 7;
        cp16(sb + (uint32_t)(row * QSTR + seg * 8) * 2,
             Qg + (size_t)row * HD + seg * 8);
    }
    cp_commit();

#define LOAD_KV(st, it) do { \
    int kvb = (it) * 128; \
    _Pragma("unroll") \
    for (int p = 0; p < 8; p++) { \
        int idx = tid + p * 256; \
        int tile = idx >> 10, row = (idx >> 3) & 127, seg = idx & 7; \
        const __nv_bfloat16* src = tile ? Vg : Kg; \
        uint32_t dst = sb + KV_OFF + (st) * KVSTAGE + tile * ATILE \
                       + (uint32_t)(row * QSTR + seg * 8) * 2; \
        cp16(dst, src + (size_t)(kvb + row) * HD + seg * 8); \
    } \
    cp_commit(); \
} while (0)

    LOAD_KV(0, 0);
    cp_wait<1>();
    __syncthreads();

    uint32_t qf[4][4];
#pragma unroll
    for (int kk = 0; kk < 4; kk++) {
        int mrow = wid * 16 + ((lane >> 3) & 1) * 8 + (lane & 7);
        int mcol = kk * 16 + (lane >> 4) * 8;
        ldm_x4(qf[kk], sb + (uint32_t)(mrow * QSTR + mcol) * 2);
    }

    float o[8][4];
#pragma unroll
    for (int nt = 0; nt < 8; nt++)
#pragma unroll
        for (int e = 0; e < 4; e++) o[nt][e] = 0.0f;
    float l0 = 0.0f, l1 = 0.0f;

    for (int it = 0; it < 16; it++) {
        if (it < 15) { LOAD_KV((it + 1) & 1, it + 1); cp_wait<1>(); }
        else         { cp_wait<0>(); }
        __syncthreads();

        const uint32_t Kb = sb + KV_OFF + (it & 1) * KVSTAGE;
        const uint32_t Vb = Kb + ATILE;

        // per 16-kv-chunk: QK (split accums) -> merge -> exp2 -> P bf16 -> PV
#pragma unroll
        for (int t = 0; t < 8; t++) {
            float s0a[4] = {0,0,0,0}, s1a[4] = {0,0,0,0};
            float s0b[4] = {0,0,0,0}, s1b[4] = {0,0,0,0};
            const int nrow = t * 16 + (lane >> 4) * 8 + (lane & 7);
#pragma unroll
            for (int kk = 0; kk < 2; kk++) {
                int ncol = kk * 16 + ((lane >> 3) & 1) * 8;
                uint32_t r[4];
                ldm_x4(r, Kb + (uint32_t)(nrow * QSTR + ncol) * 2);
                mma_bf16(s0a, qf[kk], r);
                mma_bf16(s1a, qf[kk], r + 2);
            }
#pragma unroll
            for (int kk = 2; kk < 4; kk++) {
                int ncol = kk * 16 + ((lane >> 3) & 1) * 8;
                uint32_t r[4];
                ldm_x4(r, Kb + (uint32_t)(nrow * QSTR + ncol) * 2);
                mma_bf16(s0b, qf[kk], r);
                mma_bf16(s1b, qf[kk], r + 2);
            }
            float s0[4], s1[4];
#pragma unroll
            for (int e = 0; e < 4; e++) { s0[e] = s0a[e] + s0b[e]; s1[e] = s1a[e] + s1b[e]; }

            s0[0] = exp2_nomax(s0[0]); s0[1] = exp2_nomax(s0[1]);
            s0[2] = exp2_nomax(s0[2]); s0[3] = exp2_nomax(s0[3]);
            s1[0] = exp2_nomax(s1[0]); s1[1] = exp2_nomax(s1[1]);
            s1[2] = exp2_nomax(s1[2]); s1[3] = exp2_nomax(s1[3]);
            l0 += s0[0] + s0[1] + s1[0] + s1[1];
            l1 += s0[2] + s0[3] + s1[2] + s1[3];

            uint32_t pa[4];
            asm("cvt.rn.bf16x2.f32 %0, %1, %2;" : "=r"(pa[0]) : "f"(s0[1]), "f"(s0[0]));
            asm("cvt.rn.bf16x2.f32 %0, %1, %2;" : "=r"(pa[1]) : "f"(s0[3]), "f"(s0[2]));
            asm("cvt.rn.bf16x2.f32 %0, %1, %2;" : "=r"(pa[2]) : "f"(s1[1]), "f"(s1[0]));
            asm("cvt.rn.bf16x2.f32 %0, %1, %2;" : "=r"(pa[3]) : "f"(s1[3]), "f"(s1[2]));

            const int kvrow = t * 16 + ((lane >> 3) & 1) * 8 + (lane & 7);
#pragma unroll
            for (int nh = 0; nh < 4; nh++) {
                int col = nh * 16 + (lane >> 4) * 8;
                uint32_t r[4];
                ldm_x4_t(r, Vb + (uint32_t)(kvrow * QSTR + col) * 2);
                mma_bf16(o[nh * 2],     pa, r);
                mma_bf16(o[nh * 2 + 1], pa, r + 2);
            }
        }
        __syncthreads();
    }

    // reduce l over the tig group once
    l0 += __shfl_xor_sync(0xffffffffu, l0, 1);
    l0 += __shfl_xor_sync(0xffffffffu, l0, 2);
    l1 += __shfl_xor_sync(0xffffffffu, l1, 1);
    l1 += __shfl_xor_sync(0xffffffffu, l1, 2);

    const float rl0 = 1.0f / l0, rl1 = 1.0f / l1;
    const size_t row0 = (size_t)(b * SS + q0 + wid * 16 + gid) * HD;
    const size_t row1 = row0 + 8 * HD;
#pragma unroll
    for (int nt = 0; nt < 8; nt++) {
        int col = h * DD + nt * 8 + 2 * tig;
        *(__nv_bfloat162*)(g_AttnH + row0 + col) =
            __halves2bfloat162(__float2bfloat16(o[nt][0] * rl0),
                               __float2bfloat16(o[nt][1] * rl0));
        *(__nv_bfloat162*)(g_AttnH + row1 + col) =
            __halves2bfloat162(__float2bfloat16(o[nt][2] * rl1),
                               __float2bfloat16(o[nt][3] * rl1));
    }
}

// ---------------------------------------------------------------------------
extern "C" void kernel_launch(void* const* d_in, const int* in_sizes, int n_in,
                              void* d_out, int out_size)
{
    const float* emb  = (const float*)d_in[0];
    const float* Wq   = (const float*)d_in[1];
    const float* Wk   = (const float*)d_in[2];
    const float* Wv   = (const float*)d_in[3];
    const float* Wu   = (const float*)d_in[4];
    const float* bu   = (const float*)d_in[5];
    const float* qn_w = (const float*)d_in[6];
    const float* qn_b = (const float*)d_in[7];
    const float* kn_w = (const float*)d_in[8];
    const float* kn_b = (const float*)d_in[9];
    float* out = (float*)d_out;

    (void)in_sizes; (void)n_in; (void)out_size;

    cudaFuncSetAttribute(attn_kernel,
                         cudaFuncAttributeMaxDynamicSharedMemorySize, ATTN_SMEM);
    cudaFuncSetAttribute(mma_gemm_kernel,
                         cudaFuncAttributeMaxDynamicSharedMemorySize, GEMM_SMEM);

    __nv_bfloat16 *EmbH_p, *AttnH_p, *Wh_p;
    cudaGetSymbolAddress((void**)&EmbH_p, g_EmbH);
    cudaGetSymbolAddress((void**)&AttnH_p, g_AttnH);
    cudaGetSymbolAddress((void**)&Wh_p, g_Wh);

    // 1) emb + all weights -> bf16 (single launch)
    conv_all_kernel<<<dim3((EE * HD / 8) / 256, 8), 256>>>(Wq, Wk, Wv, Wu, emb);

    // 2) QKV projections with fused LayerNorm epilogue -> Qh/Kh/Vh (bf16)
    mma_gemm_kernel<<<dim3(HD / 128, MTOT / 128, 3), 256, GEMM_SMEM>>>(
        EmbH_p, Wh_p, nullptr, nullptr, nullptr, qn_w, qn_b, kn_w, kn_b);

    // 3) Attention (tensor cores + max-free FMA-pipe exp2) -> g_AttnH (bf16)
    attn_kernel<<<dim3(SS / 128, BB * HH), 256, ATTN_SMEM>>>();

    // 4) Output projection + bias + residual
    mma_gemm_kernel<<<dim3(EE / 128, MTOT / 128, 1), 256, GEMM_SMEM>>>(
        AttnH_p, Wh_p + (size_t)3 * EE * HD, out, emb, bu,
        nullptr, nullptr, nullptr, nullptr);
}

// round 17
// speedup vs baseline: 1.0488x; 1.0488x over previous
#include <cuda_runtime.h>
#include <cuda_bf16.h>
#include <cstdint>

#define BB 2
#define SS 2048
#define EE 1024
#define HH 16
#define DD 64
#define MTOT (BB*SS)    // 4096
#define HD (HH*DD)      // 1024

// bf16 operands
__device__ __nv_bfloat16 g_Qh[(size_t)MTOT * HD];
__device__ __nv_bfloat16 g_Kh[(size_t)MTOT * HD];
__device__ __nv_bfloat16 g_Vh[(size_t)MTOT * HD];
__device__ __nv_bfloat16 g_EmbH[(size_t)MTOT * HD];   // emb bf16 (QKV A operand)
__device__ __nv_bfloat16 g_AttnH[(size_t)MTOT * HD];  // attn out bf16 (out-proj A)
// weights bf16: Wq @0, Wk @1M, Wv @2M, Wu @3M
__device__ __nv_bfloat16 g_Wh[(size_t)4 * EE * HD];

// ===========================================================================
// helpers (arch-portable: cp.async + ldmatrix + mma.sync, sm_80+ PTX)
// ===========================================================================
__device__ __forceinline__ uint32_t smem_to_u32(const void* p) {
    uint32_t a;
    asm("{ .reg .u64 t; cvta.to.shared.u64 t, %1; cvt.u32.u64 %0, t; }"
        : "=r"(a) : "l"(p));
    return a;
}
__device__ __forceinline__ void cp16(uint32_t d, const void* s) {
    asm volatile("cp.async.ca.shared.global [%0], [%1], 16;" :: "r"(d), "l"(s));
}
__device__ __forceinline__ void cp_commit() {
    asm volatile("cp.async.commit_group;" ::: "memory");
}
template <int N>
__device__ __forceinline__ void cp_wait() {
    asm volatile("cp.async.wait_group %0;" :: "n"(N) : "memory");
}
__device__ __forceinline__ void ldm_x4(uint32_t* r, uint32_t addr) {
    asm volatile("ldmatrix.sync.aligned.m8n8.x4.shared.b16 {%0,%1,%2,%3}, [%4];"
        : "=r"(r[0]), "=r"(r[1]), "=r"(r[2]), "=r"(r[3]) : "r"(addr));
}
__device__ __forceinline__ void ldm_x4_t(uint32_t* r, uint32_t addr) {
    asm volatile("ldmatrix.sync.aligned.m8n8.x4.trans.shared.b16 {%0,%1,%2,%3}, [%4];"
        : "=r"(r[0]), "=r"(r[1]), "=r"(r[2]), "=r"(r[3]) : "r"(addr));
}
__device__ __forceinline__ void mma_bf16(float* d, const uint32_t* a, const uint32_t* b) {
    asm volatile(
        "mma.sync.aligned.m16n8k16.row.col.f32.bf16.bf16.f32 "
        "{%0,%1,%2,%3}, {%4,%5,%6,%7}, {%8,%9}, {%0,%1,%2,%3};"
        : "+f"(d[0]), "+f"(d[1]), "+f"(d[2]), "+f"(d[3])
        : "r"(a[0]), "r"(a[1]), "r"(a[2]), "r"(a[3]), "r"(b[0]), "r"(b[1]));
}
// 2^y, degree-4 Taylor on [-0.5,0.5] (rel err ~6e-5). |y| bounded by LN'd Q/K.
__device__ __forceinline__ float exp2_nomax(float y) {
    float t = y + 12582912.0f;                 // 1.5*2^23: round-to-nearest
    int ibits = __float_as_int(t) << 23;
    float f = y - (t - 12582912.0f);           // f in [-0.5, 0.5]
    float p = 9.6181e-3f;
    p = fmaf(p, f, 5.5504108664e-2f);
    p = fmaf(p, f, 2.4022650696e-1f);
    p = fmaf(p, f, 6.9314718056e-1f);
    p = fmaf(p, f, 1.0f);
    return __int_as_float(__float_as_int(p) + ibits);
}

// ===========================================================================
// fp32 -> bf16 conversion: ONE kernel for all weights + emb.
// ===========================================================================
__global__ __launch_bounds__(256) void conv_all_kernel(
    const float* __restrict__ Wq, const float* __restrict__ Wk,
    const float* __restrict__ Wv, const float* __restrict__ Wu,
    const float* __restrict__ emb)
{
    const int z = blockIdx.y;
    const size_t M1 = (size_t)EE * HD;  // 1M elements
    const float* src;
    __nv_bfloat16* dst;
    if (z < 4) {
        src = (z == 0) ? Wq : (z == 1) ? Wk : (z == 2) ? Wv : Wu;
        dst = g_Wh + (size_t)z * M1;
    } else {
        src = emb + (size_t)(z - 4) * M1;
        dst = g_EmbH + (size_t)(z - 4) * M1;
    }
    int i = blockIdx.x * blockDim.x + threadIdx.x;   // over 1M/8
    float4 a = ((const float4*)src)[2 * i + 0];
    float4 b = ((const float4*)src)[2 * i + 1];
    __nv_bfloat162* d = (__nv_bfloat162*)dst + 4 * i;
    d[0] = __halves2bfloat162(__float2bfloat16(a.x), __float2bfloat16(a.y));
    d[1] = __halves2bfloat162(__float2bfloat16(a.z), __float2bfloat16(a.w));
    d[2] = __halves2bfloat162(__float2bfloat16(b.x), __float2bfloat16(b.y));
    d[3] = __halves2bfloat162(__float2bfloat16(b.z), __float2bfloat16(b.w));
}

// ===========================================================================
// bf16 mma.sync GEMM — R14-exact (measured best): block 128x128, BK=32,
// 8 warps, 3-stage cp.async, ONE barrier per k-iter, launch_bounds(256,2).
// ===========================================================================
#define ASTR 40
#define TILE_BYTES (128 * ASTR * 2)       // 10240
#define STAGE_BYTES (2 * TILE_BYTES)      // 20480
#define NSTAGE 3
#define GEMM_SMEM (NSTAGE * STAGE_BYTES)  // 61440

__global__ __launch_bounds__(256, 2) void mma_gemm_kernel(
    const __nv_bfloat16* __restrict__ A,
    const __nv_bfloat16* __restrict__ Wall,
    float* Cout,
    const float* __restrict__ emb, const float* __restrict__ bu,
    const float* __restrict__ qn_w, const float* __restrict__ qn_b,
    const float* __restrict__ kn_w, const float* __restrict__ kn_b)
{
    extern __shared__ char smem[];
    const uint32_t sb = smem_to_u32(smem);
    const int tid = threadIdx.x;
    const int wid = tid >> 5, lane = tid & 31;
    const int bn = blockIdx.x * 128;
    const int bm = blockIdx.y * 128;
    const int z = blockIdx.z;

    const __nv_bfloat16* Bp = Wall + (size_t)z * EE * HD;
    const int wm = wid & 3;
    const int wn = wid >> 2;

    float acc[2][8][4];
#pragma unroll
    for (int mt = 0; mt < 2; mt++)
#pragma unroll
        for (int nt = 0; nt < 8; nt++)
#pragma unroll
            for (int e = 0; e < 4; e++) acc[mt][nt][e] = 0.0f;

#define LOAD_STAGE(st, kt) do { \
    _Pragma("unroll") \
    for (int it = 0; it < 4; it++) { \
        int idx = tid + it * 256; \
        int tile = idx >> 9, rem = idx & 511, row = rem >> 2, seg = rem & 3; \
        const __nv_bfloat16* srcp = tile ? Bp : A; \
        int grow = (tile ? bn : bm) + row; \
        uint32_t dst = sb + (st) * STAGE_BYTES + tile * TILE_BYTES \
                       + (uint32_t)(row * ASTR + seg * 8) * 2; \
        cp16(dst, srcp + (size_t)grow * 1024 + (kt) + seg * 8); \
    } \
    cp_commit(); \
} while (0)

    LOAD_STAGE(0, 0);
    LOAD_STAGE(1, 32);

    int stage = 0;
    for (int ch = 0; ch < 32; ch++) {
        if (ch < 31) cp_wait<1>();
        else         cp_wait<0>();
        __syncthreads();   // single barrier per iteration

        const uint32_t aA = sb + stage * STAGE_BYTES;
        const uint32_t aB = aA + TILE_BYTES;

#pragma unroll
        for (int kk = 0; kk < 2; kk++) {
            const int k0 = kk * 16;
            uint32_t ah[2][4], bh[8][2];
#pragma unroll
            for (int mt = 0; mt < 2; mt++) {
                int mrow = wm * 32 + mt * 16 + ((lane >> 3) & 1) * 8 + (lane & 7);
                int mcol = k0 + (lane >> 4) * 8;
                ldm_x4(ah[mt], aA + (uint32_t)(mrow * ASTR + mcol) * 2);
            }
#pragma unroll
            for (int np = 0; np < 4; np++) {
                int nrow = wn * 64 + np * 16 + (lane >> 4) * 8 + (lane & 7);
                int ncol = k0 + ((lane >> 3) & 1) * 8;
                uint32_t r[4];
                ldm_x4(r, aB + (uint32_t)(nrow * ASTR + ncol) * 2);
                bh[np * 2][0] = r[0]; bh[np * 2][1] = r[1];
                bh[np * 2 + 1][0] = r[2]; bh[np * 2 + 1][1] = r[3];
            }
#pragma unroll
            for (int mt = 0; mt < 2; mt++)
#pragma unroll
                for (int nt = 0; nt < 8; nt++) mma_bf16(acc[mt][nt], ah[mt], bh[nt]);
        }

        if (ch < 30) {
            int nst = stage + 2; if (nst >= NSTAGE) nst -= NSTAGE;
            LOAD_STAGE(nst, (ch + 2) * 32);
        }
        if (++stage == NSTAGE) stage = 0;
    }

    const int tig = lane & 3, gid = lane >> 2;
    if (z == 2) {
#pragma unroll
        for (int mt = 0; mt < 2; mt++) {
            int r0 = bm + wm * 32 + mt * 16 + gid;
#pragma unroll
            for (int nt = 0; nt < 8; nt++) {
                int n = bn + wn * 64 + nt * 8 + tig * 2;
                *(__nv_bfloat162*)(g_Vh + (size_t)r0 * HD + n) =
                    __halves2bfloat162(__float2bfloat16(acc[mt][nt][0]),
                                       __float2bfloat16(acc[mt][nt][1]));
                *(__nv_bfloat162*)(g_Vh + (size_t)(r0 + 8) * HD + n) =
                    __halves2bfloat162(__float2bfloat16(acc[mt][nt][2]),
                                       __float2bfloat16(acc[mt][nt][3]));
            }
        }
    } else if (emb) {
#pragma unroll
        for (int mt = 0; mt < 2; mt++) {
            int r0 = bm + wm * 32 + mt * 16 + gid;
#pragma unroll
            for (int nt = 0; nt < 8; nt++) {
                int n = bn + wn * 64 + nt * 8 + tig * 2;
                float2 v0 = make_float2(acc[mt][nt][0], acc[mt][nt][1]);
                float2 v1 = make_float2(acc[mt][nt][2], acc[mt][nt][3]);
                float b0 = bu[n], b1 = bu[n + 1];
                float2 e0 = *(const float2*)(emb + (size_t)r0 * EE + n);
                float2 e1 = *(const float2*)(emb + (size_t)(r0 + 8) * EE + n);
                v0.x += b0 + e0.x; v0.y += b1 + e0.y;
                v1.x += b0 + e1.x; v1.y += b1 + e1.y;
                *(float2*)(Cout + (size_t)r0 * 1024 + n) = v0;
                *(float2*)(Cout + (size_t)(r0 + 8) * 1024 + n) = v1;
            }
        }
    } else {
        const float scale = (z == 0) ? 0.1803368801111243f : 1.0f;
        const float* lw = (z == 0) ? qn_w : kn_w;
        const float* lb = (z == 0) ? qn_b : kn_b;
        __nv_bfloat16* dstb = (z == 0) ? g_Qh : g_Kh;
        float wv[16], bv[16];
#pragma unroll
        for (int nt = 0; nt < 8; nt++) {
            int c = nt * 8 + tig * 2;
            float2 wp = *(const float2*)(lw + c);
            float2 bp = *(const float2*)(lb + c);
            wv[nt * 2] = wp.x; wv[nt * 2 + 1] = wp.y;
            bv[nt * 2] = bp.x; bv[nt * 2 + 1] = bp.y;
        }
#pragma unroll
        for (int mt = 0; mt < 2; mt++) {
            int r0 = bm + wm * 32 + mt * 16 + gid;
#pragma unroll
            for (int half = 0; half < 2; half++) {
                float sum = 0.0f, sq = 0.0f;
#pragma unroll
                for (int nt = 0; nt < 8; nt++) {
                    float v0 = acc[mt][nt][half * 2];
                    float v1 = acc[mt][nt][half * 2 + 1];
                    sum += v0 + v1;
                    sq = fmaf(v0, v0, sq); sq = fmaf(v1, v1, sq);
                }
                sum += __shfl_xor_sync(0xffffffffu, sum, 1);
                sum += __shfl_xor_sync(0xffffffffu, sum, 2);
                sq  += __shfl_xor_sync(0xffffffffu, sq, 1);
                sq  += __shfl_xor_sync(0xffffffffu, sq, 2);
                float mean = sum * (1.0f / 64.0f);
                float var = sq * (1.0f / 64.0f) - mean * mean;
                float inv = rsqrtf(var + 1e-5f) * scale;
                int row = r0 + half * 8;
#pragma unroll
                for (int nt = 0; nt < 8; nt++) {
                    int n = bn + wn * 64 + nt * 8 + tig * 2;
                    float v0 = acc[mt][nt][half * 2];
                    float v1 = acc[mt][nt][half * 2 + 1];
                    float y0 = fmaf((v0 - mean) * inv, wv[nt * 2],     bv[nt * 2] * scale);
                    float y1 = fmaf((v1 - mean) * inv, wv[nt * 2 + 1], bv[nt * 2 + 1] * scale);
                    *(__nv_bfloat162*)(dstb + (size_t)row * HD + n) =
                        __halves2bfloat162(__float2bfloat16(y0), __float2bfloat16(y1));
                }
            }
        }
    }
}

// ---------------------------------------------------------------------------
// Flash attention on mma.sync (bf16). WIDE-Q variant: each warp owns 32 q rows
// (2 fragment sets), so every K fragment feeds 2 QK mmas and every V fragment
// 4 PV mmas — halves ldmatrix + cp.async traffic per unit tensor work
// (attn profile showed L1=51% as the top counter). CTA covers 256 q rows;
// grid (S/256, B*H) = 256 CTAs; launch_bounds(256,1).
// Max-free softmax; output bf16 into g_AttnH.
// ---------------------------------------------------------------------------
#define QSTR 72
#define QTILE (256 * QSTR * 2)          // 36864: Q, 256 rows
#define ATILE (128 * QSTR * 2)          // 18432: one 128-row KV tile
#define KV_OFF QTILE
#define KVSTAGE (2 * ATILE)
#define ATTN_SMEM (QTILE + 2 * KVSTAGE) // 110592

__global__ __launch_bounds__(256, 1) void attn_kernel()
{
    extern __shared__ char smem[];
    const uint32_t sb = smem_to_u32(smem);
    const int tid = threadIdx.x;
    const int wid = tid >> 5, lane = tid & 31;
    const int gid = lane >> 2, tig = lane & 3;
    const int q0 = blockIdx.x * 256;
    const int bh = blockIdx.y;
    const int b = bh >> 4, h = bh & 15;

    const __nv_bfloat16* Qg = g_Qh + (size_t)(b * SS + q0) * HD + h * DD;
    const __nv_bfloat16* Kg = g_Kh + (size_t)(b * SS) * HD + h * DD;
    const __nv_bfloat16* Vg = g_Vh + (size_t)(b * SS) * HD + h * DD;

    // load Q tile: 256 rows x 64 cols = 2048 chunks of 16B
#pragma unroll
    for (int p = 0; p < 8; p++) {
        int idx = tid + p * 256;
        int row = idx >> 3, seg = idx & 7;
        cp16(sb + (uint32_t)(row * QSTR + seg * 8) * 2,
             Qg + (size_t)row * HD + seg * 8);
    }
    cp_commit();

#define LOAD_KV(st, it) do { \
    int kvb = (it) * 128; \
    _Pragma("unroll") \
    for (int p = 0; p < 8; p++) { \
        int idx = tid + p * 256; \
        int tile = idx >> 10, row = (idx >> 3) & 127, seg = idx & 7; \
        const __nv_bfloat16* src = tile ? Vg : Kg; \
        uint32_t dst = sb + KV_OFF + (st) * KVSTAGE + tile * ATILE \
                       + (uint32_t)(row * QSTR + seg * 8) * 2; \
        cp16(dst, src + (size_t)(kvb + row) * HD + seg * 8); \
    } \
    cp_commit(); \
} while (0)

    LOAD_KV(0, 0);
    cp_wait<1>();
    __syncthreads();

    // Q fragments: 2 sets of 16 rows per warp
    uint32_t qf[2][4][4];
#pragma unroll
    for (int set = 0; set < 2; set++)
#pragma unroll
        for (int kk = 0; kk < 4; kk++) {
            int mrow = wid * 32 + set * 16 + ((lane >> 3) & 1) * 8 + (lane & 7);
            int mcol = kk * 16 + (lane >> 4) * 8;
            ldm_x4(qf[set][kk], sb + (uint32_t)(mrow * QSTR + mcol) * 2);
        }

    float o[2][8][4];
#pragma unroll
    for (int set = 0; set < 2; set++)
#pragma unroll
        for (int nt = 0; nt < 8; nt++)
#pragma unroll
            for (int e = 0; e < 4; e++) o[set][nt][e] = 0.0f;
    float l[2][2] = {{0.0f, 0.0f}, {0.0f, 0.0f}};

    for (int it = 0; it < 16; it++) {
        if (it < 15) { LOAD_KV((it + 1) & 1, it + 1); cp_wait<1>(); }
        else         { cp_wait<0>(); }
        __syncthreads();

        const uint32_t Kb = sb + KV_OFF + (it & 1) * KVSTAGE;
        const uint32_t Vb = Kb + ATILE;

        // per 16-kv-chunk: K frags shared by both Q sets; V frags shared too
#pragma unroll
        for (int t = 0; t < 8; t++) {
            float s[2][2][4];
#pragma unroll
            for (int set = 0; set < 2; set++)
#pragma unroll
                for (int hp = 0; hp < 2; hp++)
#pragma unroll
                    for (int e = 0; e < 4; e++) s[set][hp][e] = 0.0f;

            const int nrow = t * 16 + (lane >> 4) * 8 + (lane & 7);
#pragma unroll
            for (int kk = 0; kk < 4; kk++) {
                int ncol = kk * 16 + ((lane >> 3) & 1) * 8;
                uint32_t r[4];
                ldm_x4(r, Kb + (uint32_t)(nrow * QSTR + ncol) * 2);
                mma_bf16(s[0][0], qf[0][kk], r);
                mma_bf16(s[1][0], qf[1][kk], r);
                mma_bf16(s[0][1], qf[0][kk], r + 2);
                mma_bf16(s[1][1], qf[1][kk], r + 2);
            }

            uint32_t pa[2][4];
#pragma unroll
            for (int set = 0; set < 2; set++) {
                float* a0 = s[set][0];
                float* a1 = s[set][1];
                a0[0] = exp2_nomax(a0[0]); a0[1] = exp2_nomax(a0[1]);
                a0[2] = exp2_nomax(a0[2]); a0[3] = exp2_nomax(a0[3]);
                a1[0] = exp2_nomax(a1[0]); a1[1] = exp2_nomax(a1[1]);
                a1[2] = exp2_nomax(a1[2]); a1[3] = exp2_nomax(a1[3]);
                l[set][0] += a0[0] + a0[1] + a1[0] + a1[1];
                l[set][1] += a0[2] + a0[3] + a1[2] + a1[3];
                asm("cvt.rn.bf16x2.f32 %0, %1, %2;" : "=r"(pa[set][0]) : "f"(a0[1]), "f"(a0[0]));
                asm("cvt.rn.bf16x2.f32 %0, %1, %2;" : "=r"(pa[set][1]) : "f"(a0[3]), "f"(a0[2]));
                asm("cvt.rn.bf16x2.f32 %0, %1, %2;" : "=r"(pa[set][2]) : "f"(a1[1]), "f"(a1[0]));
                asm("cvt.rn.bf16x2.f32 %0, %1, %2;" : "=r"(pa[set][3]) : "f"(a1[3]), "f"(a1[2]));
            }

            const int kvrow = t * 16 + ((lane >> 3) & 1) * 8 + (lane & 7);
#pragma unroll
            for (int nh = 0; nh < 4; nh++) {
                int col = nh * 16 + (lane >> 4) * 8;
                uint32_t r[4];
                ldm_x4_t(r, Vb + (uint32_t)(kvrow * QSTR + col) * 2);
                mma_bf16(o[0][nh * 2],     pa[0], r);
                mma_bf16(o[1][nh * 2],     pa[1], r);
                mma_bf16(o[0][nh * 2 + 1], pa[0], r + 2);
                mma_bf16(o[1][nh * 2 + 1], pa[1], r + 2);
            }
        }
        __syncthreads();
    }

    // reduce l over the tig group, write outputs per set
#pragma unroll
    for (int set = 0; set < 2; set++) {
        float l0 = l[set][0], l1 = l[set][1];
        l0 += __shfl_xor_sync(0xffffffffu, l0, 1);
        l0 += __shfl_xor_sync(0xffffffffu, l0, 2);
        l1 += __shfl_xor_sync(0xffffffffu, l1, 1);
        l1 += __shfl_xor_sync(0xffffffffu, l1, 2);
        const float rl0 = 1.0f / l0, rl1 = 1.0f / l1;
        const size_t row0 = (size_t)(b * SS + q0 + wid * 32 + set * 16 + gid) * HD;
        const size_t row1 = row0 + 8 * HD;
#pragma unroll
        for (int nt = 0; nt < 8; nt++) {
            int col = h * DD + nt * 8 + 2 * tig;
            *(__nv_bfloat162*)(g_AttnH + row0 + col) =
                __halves2bfloat162(__float2bfloat16(o[set][nt][0] * rl0),
                                   __float2bfloat16(o[set][nt][1] * rl0));
            *(__nv_bfloat162*)(g_AttnH + row1 + col) =
                __halves2bfloat162(__float2bfloat16(o[set][nt][2] * rl1),
                                   __float2bfloat16(o[set][nt][3] * rl1));
        }
    }
}

// ---------------------------------------------------------------------------
extern "C" void kernel_launch(void* const* d_in, const int* in_sizes, int n_in,
                              void* d_out, int out_size)
{
    const float* emb  = (const float*)d_in[0];
    const float* Wq   = (const float*)d_in[1];
    const float* Wk   = (const float*)d_in[2];
    const float* Wv   = (const float*)d_in[3];
    const float* Wu   = (const float*)d_in[4];
    const float* bu   = (const float*)d_in[5];
    const float* qn_w = (const float*)d_in[6];
    const float* qn_b = (const float*)d_in[7];
    const float* kn_w = (const float*)d_in[8];
    const float* kn_b = (const float*)d_in[9];
    float* out = (float*)d_out;

    (void)in_sizes; (void)n_in; (void)out_size;

    cudaFuncSetAttribute(attn_kernel,
                         cudaFuncAttributeMaxDynamicSharedMemorySize, ATTN_SMEM);
    cudaFuncSetAttribute(mma_gemm_kernel,
                         cudaFuncAttributeMaxDynamicSharedMemorySize, GEMM_SMEM);

    __nv_bfloat16 *EmbH_p, *AttnH_p, *Wh_p;
    cudaGetSymbolAddress((void**)&EmbH_p, g_EmbH);
    cudaGetSymbolAddress((void**)&AttnH_p, g_AttnH);
    cudaGetSymbolAddress((void**)&Wh_p, g_Wh);

    // 1) emb + all weights -> bf16 (single launch)
    conv_all_kernel<<<dim3((EE * HD / 8) / 256, 8), 256>>>(Wq, Wk, Wv, Wu, emb);

    // 2) QKV projections with fused LayerNorm epilogue -> Qh/Kh/Vh (bf16)
    mma_gemm_kernel<<<dim3(HD / 128, MTOT / 128, 3), 256, GEMM_SMEM>>>(
        EmbH_p, Wh_p, nullptr, nullptr, nullptr, qn_w, qn_b, kn_w, kn_b);

    // 3) Attention (wide-Q, tensor cores + max-free exp2) -> g_AttnH (bf16)
    attn_kernel<<<dim3(SS / 256, BB * HH), 256, ATTN_SMEM>>>();

    // 4) Output projection + bias + residual
    mma_gemm_kernel<<<dim3(EE / 128, MTOT / 128, 1), 256, GEMM_SMEM>>>(
        AttnH_p, Wh_p + (size_t)3 * EE * HD, out, emb, bu,
        nullptr, nullptr, nullptr, nullptr);
}